// round 14
// baseline (speedup 1.0000x reference)
#include <cuda_runtime.h>

#define NN 100000
#define DV2 32                               // 64 floats = 32 float2/row
#define GROUP 256                            // nodes per gather block
#define NGROUP ((NN + GROUP - 1) / GROUP)    // 391
#define EPB 8192                             // edges per radix block
#define RUNCAP 4608                          // smem cap per group (mean 3200, 25 sigma)

__device__ int   g_outdeg[NN];
__device__ float g_norml[NN];
__device__ int   g_gcnt[NGROUP];
__device__ int   g_goff[NGROUP];
__device__ int   g_gcur[NGROUP];
__device__ int   g_packed[1250016];          // packed (src | dlocal<<17)

__global__ void k_count_out(const int* __restrict__ src, int e) {
    int i = blockIdx.x * blockDim.x + threadIdx.x;
    if (i < e) atomicAdd(&g_outdeg[src[i]], 1);
}

__global__ void k_norml() {
    int i = blockIdx.x * blockDim.x + threadIdx.x;
    if (i < NN) g_norml[i] = rsqrtf(fmaxf((float)g_outdeg[i], 1.f) + 1.f);
}

// Coarse histogram of dst>>8: smem bins, one global atomic per (block,bucket).
__global__ void __launch_bounds__(256) k_bucket_count(const int* __restrict__ dst, int e) {
    __shared__ int h[NGROUP];
    for (int i = threadIdx.x; i < NGROUP; i += 256) h[i] = 0;
    __syncthreads();
    int beg = blockIdx.x * EPB, end = min(e, beg + EPB);
    for (int i = beg + threadIdx.x; i < end; i += 256)
        atomicAdd(&h[dst[i] >> 8], 1);
    __syncthreads();
    for (int i = threadIdx.x; i < NGROUP; i += 256)
        if (h[i]) atomicAdd(&g_gcnt[i], h[i]);
}

// Exclusive scan of the 391 bucket totals (1 block).
__global__ void k_scan() {
    __shared__ int sh[512];
    int tid = threadIdx.x;
    int v = (tid < NGROUP) ? g_gcnt[tid] : 0;
    sh[tid] = v;
    __syncthreads();
    for (int off = 1; off < 512; off <<= 1) {
        int t = (tid >= off) ? sh[tid - off] : 0;
        __syncthreads();
        sh[tid] += t;
        __syncthreads();
    }
    if (tid < NGROUP) { int o = sh[tid] - v; g_goff[tid] = o; g_gcur[tid] = o; }
}

// Scatter packed records into per-group runs. Per-block base reservation:
// one global atomic per (block,bucket); slot assignment via smem cursors.
__global__ void __launch_bounds__(256) k_scatter(const int* __restrict__ src,
                                                 const int* __restrict__ dst, int e) {
    __shared__ int h[NGROUP], base[NGROUP], cur[NGROUP];
    for (int i = threadIdx.x; i < NGROUP; i += 256) h[i] = 0;
    __syncthreads();
    int beg = blockIdx.x * EPB, end = min(e, beg + EPB);
    for (int i = beg + threadIdx.x; i < end; i += 256)
        atomicAdd(&h[dst[i] >> 8], 1);
    __syncthreads();
    for (int i = threadIdx.x; i < NGROUP; i += 256) {
        base[i] = h[i] ? atomicAdd(&g_gcur[i], h[i]) : 0;
        cur[i] = 0;
    }
    __syncthreads();
    for (int i = beg + threadIdx.x; i < end; i += 256) {
        int d = dst[i], s = src[i];
        int b = d >> 8;
        int p = base[b] + atomicAdd(&cur[b], 1);
        g_packed[p] = s | ((d & 255) << 17);
    }
}

// One block per 256-node group: sort the group's run by node in SMEM, then
// warp-per-node float2 gather with indices served from SMEM.
__global__ void __launch_bounds__(256) k_gather(const float2* __restrict__ feat,
                                                float2* __restrict__ out) {
    __shared__ int scnt[GROUP], sstart[GROUP], scur[GROUP];
    __shared__ int ssorted[RUNCAP];
    int g = blockIdx.x;
    int tid = threadIdx.x;
    int runbeg = g_goff[g];
    int runlen = g_gcnt[g];
    if (runlen > RUNCAP) runlen = RUNCAP;        // statistically unreachable

    scnt[tid] = 0;
    __syncthreads();
    for (int i = tid; i < runlen; i += 256)
        atomicAdd(&scnt[g_packed[runbeg + i] >> 17], 1);
    __syncthreads();

    // exclusive block scan over 256 counters
    int v = scnt[tid];
    sstart[tid] = v;
    __syncthreads();
    for (int off = 1; off < 256; off <<= 1) {
        int t = (tid >= off) ? sstart[tid - off] : 0;
        __syncthreads();
        sstart[tid] += t;
        __syncthreads();
    }
    int excl = sstart[tid] - v;
    sstart[tid] = excl;
    scur[tid] = excl;
    __syncthreads();

    for (int i = tid; i < runlen; i += 256) {
        int p = g_packed[runbeg + i];
        int pos = atomicAdd(&scur[p >> 17], 1);
        ssorted[pos] = p & 0x1FFFF;
    }
    __syncthreads();

    int wid = tid >> 5, lane = tid & 31;
    for (int l = wid * 32; l < wid * 32 + 32; l++) {
        int node = g * GROUP + l;
        if (node >= NN) break;
        int cnt = scnt[l];
        int s0 = sstart[l];
        float hx = 0.f, hy = 0.f;
        int j = 0;
        for (; j + 3 < cnt; j += 4) {
            int a = ssorted[s0 + j];
            int b = ssorted[s0 + j + 1];
            int c = ssorted[s0 + j + 2];
            int d = ssorted[s0 + j + 3];
            float2 v0 = __ldg(&feat[a * DV2 + lane]);
            float2 v1 = __ldg(&feat[b * DV2 + lane]);
            float2 v2 = __ldg(&feat[c * DV2 + lane]);
            float2 v3 = __ldg(&feat[d * DV2 + lane]);
            float n0 = __ldg(&g_norml[a]);
            float n1 = __ldg(&g_norml[b]);
            float n2 = __ldg(&g_norml[c]);
            float n3 = __ldg(&g_norml[d]);
            hx += v0.x * n0 + v1.x * n1 + v2.x * n2 + v3.x * n3;
            hy += v0.y * n0 + v1.y * n1 + v2.y * n2 + v3.y * n3;
        }
        for (; j < cnt; j++) {
            int s = ssorted[s0 + j];
            float2 vv = __ldg(&feat[s * DV2 + lane]);
            float nl = __ldg(&g_norml[s]);
            hx += vv.x * nl;
            hy += vv.y * nl;
        }
        float nr = rsqrtf(fmaxf((float)cnt, 1.f) + 1.f);
        float2 f = __ldg(&feat[node * DV2 + lane]);
        out[node * DV2 + lane] = make_float2((f.x + hx) * nr, (f.y + hy) * nr);
    }
}

extern "C" void kernel_launch(void* const* d_in, const int* in_sizes, int n_in,
                              void* d_out, int out_size) {
    const float2* feat = (const float2*)d_in[0];
    const int*    src  = (const int*)d_in[1];
    const int*    dst  = (const int*)d_in[2];
    int e = in_sizes[1];

    void* p = nullptr;
    cudaGetSymbolAddress(&p, g_outdeg);
    cudaMemsetAsync(p, 0, NN * sizeof(int));
    cudaGetSymbolAddress(&p, g_gcnt);
    cudaMemsetAsync(p, 0, NGROUP * sizeof(int));

    int nblk = (e + EPB - 1) / EPB;
    k_count_out<<<(e + 255) / 256, 256>>>(src, e);
    k_norml<<<(NN + 255) / 256, 256>>>();
    k_bucket_count<<<nblk, 256>>>(dst, e);
    k_scan<<<1, 512>>>();
    k_scatter<<<nblk, 256>>>(src, dst, e);
    k_gather<<<NGROUP, 256>>>(feat, (float2*)d_out);
}

// round 17
// speedup vs baseline: 1.4075x; 1.4075x over previous
#include <cuda_runtime.h>

#define NN 100000
#define DV2 32                               // 64 floats = 32 float2/row
#define GROUP 256                            // nodes per group
#define NGROUP ((NN + GROUP - 1) / GROUP)    // 391
#define GCAP 4096                            // padded run capacity (mean 3200)
#define EPB 4096                             // edges per scatter block

__device__ int   g_outdeg[NN];
__device__ float g_norml[NN];
__device__ int   g_gcur[NGROUP];
__device__ int   g_packed[NGROUP * GCAP];    // src | dlocal<<17, 6.4 MB
__device__ int   g_sorted[NGROUP * GCAP];    // node-sorted src indices
__device__ int   g_rowstart[NN];
__device__ int   g_indeg[NN];

__global__ void k_norml() {
    int i = blockIdx.x * blockDim.x + threadIdx.x;
    if (i < NN) g_norml[i] = rsqrtf(fmaxf((float)g_outdeg[i], 1.f) + 1.f);
}

// Bin edges by dst-group (391 bins). smem histogram -> one global atomic per
// (block,bucket) for base reservation -> smem cursor slot assignment ->
// coalesced-run packed writes. Also counts out-degree (fire-and-forget RED).
__global__ void __launch_bounds__(256) k_scatter(const int* __restrict__ src,
                                                 const int* __restrict__ dst, int e) {
    __shared__ int h[NGROUP], base[NGROUP], cur[NGROUP];
    for (int i = threadIdx.x; i < NGROUP; i += 256) h[i] = 0;
    __syncthreads();
    int beg = blockIdx.x * EPB, end = min(e, beg + EPB);
    for (int i = beg + threadIdx.x; i < end; i += 256) {
        atomicAdd(&g_outdeg[src[i]], 1);
        atomicAdd(&h[dst[i] >> 8], 1);
    }
    __syncthreads();
    for (int i = threadIdx.x; i < NGROUP; i += 256) {
        base[i] = h[i] ? atomicAdd(&g_gcur[i], h[i]) : 0;
        cur[i] = 0;
    }
    __syncthreads();
    for (int i = beg + threadIdx.x; i < end; i += 256) {
        int d = dst[i], s = src[i];
        int b = d >> 8;
        int p = base[b] + atomicAdd(&cur[b], 1);
        if (p < GCAP) g_packed[b * GCAP + p] = s | ((d & 255) << 17);
    }
}

// One block per group: smem histogram over the 256 local nodes, block scan,
// place -> node-sorted global index array + exact rowstart/indeg per node.
__global__ void __launch_bounds__(256) k_sortgroups() {
    __shared__ int scnt[GROUP], sstart[GROUP], scur[GROUP];
    int g = blockIdx.x, tid = threadIdx.x;
    int runlen = min(g_gcur[g], GCAP);
    const int* run = g_packed + g * GCAP;

    scnt[tid] = 0;
    __syncthreads();
    for (int i = tid; i < runlen; i += 256)
        atomicAdd(&scnt[run[i] >> 17], 1);
    __syncthreads();

    int v = scnt[tid];
    sstart[tid] = v;
    __syncthreads();
    for (int off = 1; off < 256; off <<= 1) {
        int t = (tid >= off) ? sstart[tid - off] : 0;
        __syncthreads();
        sstart[tid] += t;
        __syncthreads();
    }
    int excl = sstart[tid] - v;
    scur[tid] = excl;
    __syncthreads();

    int* outp = g_sorted + g * GCAP;
    for (int i = tid; i < runlen; i += 256) {
        int p = run[i];
        int pos = atomicAdd(&scur[p >> 17], 1);
        outp[pos] = p & 0x1FFFF;
    }

    int node = g * GROUP + tid;
    if (node < NN) {
        g_rowstart[node] = g * GCAP + excl;
        g_indeg[node] = v;
    }
}

// R11's winning gather: warp per node, float2 per lane, unroll x8, norml LUT.
// Indices now come from the node-sorted array (contiguous per node).
__global__ void __launch_bounds__(256) k_gather(const float2* __restrict__ feat,
                                                float2* __restrict__ out) {
    int t = blockIdx.x * blockDim.x + threadIdx.x;
    int node = t >> 5;
    int lane = t & 31;
    if (node >= NN) return;

    int cnt = __ldg(&g_indeg[node]);
    const int* row = g_sorted + __ldg(&g_rowstart[node]);

    float hx = 0.f, hy = 0.f;
    int j = 0;
    for (; j + 7 < cnt; j += 8) {
        int a0 = __ldg(row + j);
        int a1 = __ldg(row + j + 1);
        int a2 = __ldg(row + j + 2);
        int a3 = __ldg(row + j + 3);
        int a4 = __ldg(row + j + 4);
        int a5 = __ldg(row + j + 5);
        int a6 = __ldg(row + j + 6);
        int a7 = __ldg(row + j + 7);
        float2 v0 = __ldg(&feat[a0 * DV2 + lane]);
        float2 v1 = __ldg(&feat[a1 * DV2 + lane]);
        float2 v2 = __ldg(&feat[a2 * DV2 + lane]);
        float2 v3 = __ldg(&feat[a3 * DV2 + lane]);
        float2 v4 = __ldg(&feat[a4 * DV2 + lane]);
        float2 v5 = __ldg(&feat[a5 * DV2 + lane]);
        float2 v6 = __ldg(&feat[a6 * DV2 + lane]);
        float2 v7 = __ldg(&feat[a7 * DV2 + lane]);
        float n0 = __ldg(&g_norml[a0]);
        float n1 = __ldg(&g_norml[a1]);
        float n2 = __ldg(&g_norml[a2]);
        float n3 = __ldg(&g_norml[a3]);
        float n4 = __ldg(&g_norml[a4]);
        float n5 = __ldg(&g_norml[a5]);
        float n6 = __ldg(&g_norml[a6]);
        float n7 = __ldg(&g_norml[a7]);
        hx += v0.x * n0 + v1.x * n1 + v2.x * n2 + v3.x * n3
            + v4.x * n4 + v5.x * n5 + v6.x * n6 + v7.x * n7;
        hy += v0.y * n0 + v1.y * n1 + v2.y * n2 + v3.y * n3
            + v4.y * n4 + v5.y * n5 + v6.y * n6 + v7.y * n7;
    }
    for (; j + 3 < cnt; j += 4) {
        int a0 = __ldg(row + j);
        int a1 = __ldg(row + j + 1);
        int a2 = __ldg(row + j + 2);
        int a3 = __ldg(row + j + 3);
        float2 v0 = __ldg(&feat[a0 * DV2 + lane]);
        float2 v1 = __ldg(&feat[a1 * DV2 + lane]);
        float2 v2 = __ldg(&feat[a2 * DV2 + lane]);
        float2 v3 = __ldg(&feat[a3 * DV2 + lane]);
        float n0 = __ldg(&g_norml[a0]);
        float n1 = __ldg(&g_norml[a1]);
        float n2 = __ldg(&g_norml[a2]);
        float n3 = __ldg(&g_norml[a3]);
        hx += v0.x * n0 + v1.x * n1 + v2.x * n2 + v3.x * n3;
        hy += v0.y * n0 + v1.y * n1 + v2.y * n2 + v3.y * n3;
    }
    for (; j < cnt; j++) {
        int s = __ldg(row + j);
        float2 vv = __ldg(&feat[s * DV2 + lane]);
        float nl = __ldg(&g_norml[s]);
        hx += vv.x * nl;
        hy += vv.y * nl;
    }

    float nr = rsqrtf(fmaxf((float)cnt, 1.f) + 1.f);
    float2 f = __ldg(&feat[node * DV2 + lane]);
    out[node * DV2 + lane] = make_float2((f.x + hx) * nr, (f.y + hy) * nr);
}

extern "C" void kernel_launch(void* const* d_in, const int* in_sizes, int n_in,
                              void* d_out, int out_size) {
    const float2* feat = (const float2*)d_in[0];
    const int*    src  = (const int*)d_in[1];
    const int*    dst  = (const int*)d_in[2];
    int e = in_sizes[1];

    void* p = nullptr;
    cudaGetSymbolAddress(&p, g_outdeg);
    cudaMemsetAsync(p, 0, NN * sizeof(int));
    cudaGetSymbolAddress(&p, g_gcur);
    cudaMemsetAsync(p, 0, NGROUP * sizeof(int));

    int nblk = (e + EPB - 1) / EPB;
    k_scatter<<<nblk, 256>>>(src, dst, e);
    k_norml<<<(NN + 255) / 256, 256>>>();
    k_sortgroups<<<NGROUP, 256>>>();
    k_gather<<<(NN * 32 + 255) / 256, 256>>>(feat, (float2*)d_out);
}